// round 6
// baseline (speedup 1.0000x reference)
#include <cuda_runtime.h>
#include <cstdint>
#include <math.h>

// ---- problem constants ----
#define B_    4
#define NTOT  400
#define N1    256
#define N2    144
#define DIM   256
#define NH    8

// ---- scratch ----
__device__ float g_fqk[B_ * NTOT * 512];
__device__ float g_cqk[B_ * NTOT * 128];
__device__ float g_attn[B_ * NH * NTOT * 256];   // compact cross-attn rows
__device__ float g_mix[26214400];                // attn-mixed x, rows m*256
__device__ float g_w2[65536];                    // W2 = vb_w @ v_w  [i*256+d]

// ============================================================================
// pixel row maps  (m = b*25600 + w*64 + p)
// ============================================================================
__device__ __forceinline__ const float* pixel_ptr(const float* __restrict__ x1,
                                                  const float* __restrict__ x2, int m) {
    int b = m / 25600;
    int r = m % 25600;
    int w = r >> 6;
    int p = r & 63;
    int py = p >> 3, px = p & 7;
    if (w < N1) {
        int y = (w >> 4) * 8 + py, xx = (w & 15) * 8 + px;
        return x1 + ((size_t)((b * 128 + y) * 128 + xx)) * DIM;
    } else {
        int w2 = w - N1;
        int y = (w2 / 12) * 8 + py, xx = (w2 % 12) * 8 + px;
        return x2 + ((size_t)((b * 96 + y) * 96 + xx)) * DIM;
    }
}
__device__ __forceinline__ float* out_pixel_ptr(float* __restrict__ out, int m) {
    int b = m / 25600;
    int r = m % 25600;
    int w = r >> 6;
    int p = r & 63;
    int py = p >> 3, px = p & 7;
    if (w < N1) {
        int y = (w >> 4) * 8 + py, xx = (w & 15) * 8 + px;
        return out + ((size_t)((b * 128 + y) * 128 + xx)) * DIM;
    } else {
        int w2 = w - N1;
        int y = (w2 / 12) * 8 + py, xx = (w2 % 12) * 8 + px;
        return out + 16777216 + ((size_t)((b * 96 + y) * 96 + xx)) * DIM;
    }
}

// ============================================================================
// K1: window means -> QK proj -> RMS.  4 windows per block.
// ============================================================================
__global__ __launch_bounds__(512) void k_embed(
    const float* __restrict__ x1, const float* __restrict__ c1,
    const float* __restrict__ x2, const float* __restrict__ c2,
    const float* __restrict__ fqk_w, const float* __restrict__ fqk_b, const float* __restrict__ fqk_g,
    const float* __restrict__ cqk_w, const float* __restrict__ cqk_b, const float* __restrict__ cqk_g)
{
    int bw = blockIdx.x;
    int b = bw / 100, wg = (bw % 100) * 4;
    __shared__ __align__(16) float favg[4][256];
    __shared__ float cavg[4][4];
    __shared__ float redf[4][16];
    __shared__ float redc[4][4];
    int t = threadIdx.x;

    {
        int tt = t & 255;
        int ws = t >> 8;
        #pragma unroll
        for (int qq = 0; qq < 2; ++qq) {
            int q = ws + qq * 2;
            int w = wg + q;
            const float* xbase;
            int rowstride;
            if (w < N1) {
                int wy = w >> 4, wx = w & 15;
                xbase = x1 + ((size_t)((b * 128 + wy * 8) * 128 + wx * 8)) * DIM;
                rowstride = 128 * DIM;
            } else {
                int w2 = w - N1;
                int wy = w2 / 12, wx = w2 % 12;
                xbase = x2 + ((size_t)((b * 96 + wy * 8) * 96 + wx * 8)) * DIM;
                rowstride = 96 * DIM;
            }
            float s = 0.f;
            #pragma unroll
            for (int py = 0; py < 8; ++py)
                #pragma unroll
                for (int px = 0; px < 8; ++px)
                    s += xbase[py * rowstride + px * DIM + tt];
            favg[q][tt] = s * (1.f / 64.f);
        }
    }
    if (t < 16) {
        int q = t >> 2, ch = t & 3;
        int w = wg + q;
        const float* cbase;
        int crowstride;
        if (w < N1) {
            int wy = w >> 4, wx = w & 15;
            cbase = c1 + ((size_t)((b * 128 + wy * 8) * 128 + wx * 8)) * 4;
            crowstride = 128 * 4;
        } else {
            int w2 = w - N1;
            int wy = w2 / 12, wx = w2 % 12;
            cbase = c2 + ((size_t)((b * 96 + wy * 8) * 96 + wx * 8)) * 4;
            crowstride = 96 * 4;
        }
        float s = 0.f;
        #pragma unroll
        for (int py = 0; py < 8; ++py)
            #pragma unroll
            for (int px = 0; px < 8; ++px)
                s += cbase[py * crowstride + px * 4 + ch];
        cavg[q][ch] = s * (1.f / 64.f);
    }
    __syncthreads();

    const float4* fw = (const float4*)(fqk_w + (size_t)t * 256);
    float raw[4];
    float bias = fqk_b[t];
    #pragma unroll
    for (int q = 0; q < 4; ++q) raw[q] = bias;
    #pragma unroll 4
    for (int d4 = 0; d4 < 64; ++d4) {
        float4 wv = fw[d4];
        #pragma unroll
        for (int q = 0; q < 4; ++q) {
            float4 av = ((const float4*)favg[q])[d4];
            raw[q] += wv.x * av.x + wv.y * av.y + wv.z * av.z + wv.w * av.w;
        }
    }
    float rawc[4];
    if (t < 128) {
        float cb = cqk_b[t];
        float w0 = cqk_w[t * 4 + 0], w1 = cqk_w[t * 4 + 1];
        float w2 = cqk_w[t * 4 + 2], w3 = cqk_w[t * 4 + 3];
        #pragma unroll
        for (int q = 0; q < 4; ++q)
            rawc[q] = cb + cavg[q][0] * w0 + cavg[q][1] * w1 + cavg[q][2] * w2 + cavg[q][3] * w3;
    }

    #pragma unroll
    for (int q = 0; q < 4; ++q) {
        float sf = raw[q] * raw[q];
        #pragma unroll
        for (int o = 16; o; o >>= 1) sf += __shfl_xor_sync(~0u, sf, o);
        if ((t & 31) == 0) redf[q][t >> 5] = sf;
    }
    if (t < 128) {
        #pragma unroll
        for (int q = 0; q < 4; ++q) {
            float sc = rawc[q] * rawc[q];
            #pragma unroll
            for (int o = 16; o; o >>= 1) sc += __shfl_xor_sync(~0u, sc, o);
            if ((t & 31) == 0) redc[q][t >> 5] = sc;
        }
    }
    __syncthreads();

    float gain = fqk_g[t];
    #pragma unroll
    for (int q = 0; q < 4; ++q) {
        float msf = 0.f;
        #pragma unroll
        for (int i = 0; i < 16; ++i) msf += redf[q][i];
        float invf = rsqrtf(msf * (1.f / 512.f) + 1e-6f);
        g_fqk[((size_t)(b * NTOT + wg + q)) * 512 + t] = raw[q] * invf * gain;
    }
    if (t < 128) {
        float cg = cqk_g[t];
        #pragma unroll
        for (int q = 0; q < 4; ++q) {
            float msc = redc[q][0] + redc[q][1] + redc[q][2] + redc[q][3];
            float invc = rsqrtf(msc * (1.f / 128.f) + 1e-6f);
            g_cqk[((size_t)(b * NTOT + wg + q)) * 128 + t] = rawc[q] * invc * cg;
        }
    }
}

// ============================================================================
// K2: W2 = vb_w @ v_w  (256x256), fp32
// ============================================================================
__global__ __launch_bounds__(256) void k_wmat(const float* __restrict__ vb_w,
                                              const float* __restrict__ v_w)
{
    int i = blockIdx.x, d = threadIdx.x;
    __shared__ float vb[256];
    vb[d] = vb_w[i * 256 + d];
    __syncthreads();
    float acc = 0.f;
    #pragma unroll 8
    for (int o = 0; o < 256; ++o) acc += vb[o] * v_w[o * 256 + d];
    g_w2[i * 256 + d] = acc;
}

// ============================================================================
// K3: scores + softmax (cross-source mask)
// ============================================================================
__global__ __launch_bounds__(128) void k_attn()
{
    int n  = blockIdx.x;
    int bh = blockIdx.y;
    int b = bh >> 3, h = bh & 7;
    int seg1 = (n >= N1);
    int colstart = seg1 ? 0 : N1;
    int cnt = seg1 ? N1 : N2;
    __shared__ float sc[256];
    __shared__ float red[4];
    int t = threadIdx.x;

    const float* qp  = g_fqk + ((size_t)(b * NTOT + n)) * 512 + h * 32;
    const float* cqp = g_cqk + ((size_t)(b * NTOT + n)) * 128 + h * 8;
    float fq[32], cq[8];
    #pragma unroll
    for (int i = 0; i < 32; ++i) fq[i] = qp[i];
    #pragma unroll
    for (int i = 0; i < 8; ++i) cq[i] = cqp[i];

    for (int m = t; m < cnt; m += 128) {
        int mg = colstart + m;
        const float* kp  = g_fqk + ((size_t)(b * NTOT + mg)) * 512 + 256 + h * 32;
        const float* ckp = g_cqk + ((size_t)(b * NTOT + mg)) * 128 + 64 + h * 8;
        float s = 0.f;
        #pragma unroll
        for (int i = 0; i < 32; ++i) s += fq[i] * kp[i];
        float s2 = 0.f;
        #pragma unroll
        for (int i = 0; i < 8; ++i) s2 += cq[i] * ckp[i];
        sc[m] = s * 0.1767766952966369f + s2 * 0.3535533905932738f;
    }
    __syncthreads();

    float mx = -1e30f;
    for (int m = t; m < cnt; m += 128) mx = fmaxf(mx, sc[m]);
    #pragma unroll
    for (int o = 16; o; o >>= 1) mx = fmaxf(mx, __shfl_xor_sync(~0u, mx, o));
    if ((t & 31) == 0) red[t >> 5] = mx;
    __syncthreads();
    mx = fmaxf(fmaxf(red[0], red[1]), fmaxf(red[2], red[3]));
    __syncthreads();

    float sum = 0.f;
    for (int m = t; m < cnt; m += 128) {
        float e = __expf(sc[m] - mx);
        sc[m] = e;
        sum += e;
    }
    #pragma unroll
    for (int o = 16; o; o >>= 1) sum += __shfl_xor_sync(~0u, sum, o);
    if ((t & 31) == 0) red[t >> 5] = sum;
    __syncthreads();
    sum = red[0] + red[1] + red[2] + red[3];
    float inv = 1.f / sum;
    float* dst = g_attn + ((size_t)(bh * NTOT + n)) * 256;
    for (int m = t; m < cnt; m += 128) dst[m] = sc[m] * inv;
}

// ============================================================================
// K4 v3: mix = attn @ x (gathered).  64x128 tiles, 128 threads, 8x8 microtile
// (rows ty*4 + {0,32}, cols tx*4 + {0,64}).  k-chunk 8, double-buffered.
// grid (16, 7, 32)
// ============================================================================
__global__ __launch_bounds__(128) void k_attnv3(const float* __restrict__ x1,
                                                const float* __restrict__ x2)
{
    int bh = blockIdx.z;
    int b = bh >> 3, h = bh & 7;
    int n0 = blockIdx.y * 64;
    int j0 = blockIdx.x * 128;
    int seg1 = (n0 >= N1);
    int colstart = seg1 ? 0 : N1;
    int kExt = seg1 ? N1 : N2;
    int nk = kExt >> 3;            // 32 or 18
    __shared__ __align__(16) float As[2][8][64];
    __shared__ __align__(16) float Bs[2][8][128];
    int tid = threadIdx.x;

    // A loader: row t&63, k-half (t>>6)*4
    int arow = tid & 63;
    int akh  = (tid >> 6) * 4;
    bool avalid = (n0 + arow) < NTOT;
    int asafe = avalid ? (n0 + arow) : (NTOT - 1);
    const float* aptr = g_attn + ((size_t)(bh * NTOT + asafe)) * 256 + akh;

    // B loader: k-row t>>4 (0..7), col (t&15)*8
    int bkr = tid >> 4;
    int bj  = (tid & 15) * 8;
    int pp = 8 * h + (j0 >> 8);
    int dbase = (j0 & 255);

    #define BROW(kt) pixel_ptr(x1, x2, b * 25600 + (colstart + (kt) * 8 + bkr) * 64 + pp)

    float4 a4 = avalid ? *(const float4*)aptr : make_float4(0.f, 0.f, 0.f, 0.f);
    const float* br = BROW(0);
    float4 b40 = *(const float4*)(br + dbase + bj);
    float4 b41 = *(const float4*)(br + dbase + bj + 4);
    #pragma unroll
    for (int i = 0; i < 4; ++i) As[0][akh + i][arow] = ((float*)&a4)[i];
    *(float4*)&Bs[0][bkr][bj] = b40;
    *(float4*)&Bs[0][bkr][bj + 4] = b41;
    __syncthreads();

    float acc[8][8];
    #pragma unroll
    for (int i = 0; i < 8; ++i)
        #pragma unroll
        for (int j = 0; j < 8; ++j) acc[i][j] = 0.f;

    int tx4 = (tid & 15) * 4;
    int ty4 = (tid >> 4) * 4;

    for (int kt = 0; kt < nk; ++kt) {
        int cur = kt & 1;
        if (kt + 1 < nk) {
            a4 = avalid ? *(const float4*)(aptr + (kt + 1) * 8) : make_float4(0.f, 0.f, 0.f, 0.f);
            const float* br2 = BROW(kt + 1);
            b40 = *(const float4*)(br2 + dbase + bj);
            b41 = *(const float4*)(br2 + dbase + bj + 4);
        }
        #pragma unroll
        for (int k = 0; k < 8; ++k) {
            float4 a0 = *(const float4*)&As[cur][k][ty4];
            float4 a1 = *(const float4*)&As[cur][k][32 + ty4];
            float4 c0 = *(const float4*)&Bs[cur][k][tx4];
            float4 c1 = *(const float4*)&Bs[cur][k][64 + tx4];
            float a[8] = {a0.x, a0.y, a0.z, a0.w, a1.x, a1.y, a1.z, a1.w};
            float bb[8] = {c0.x, c0.y, c0.z, c0.w, c1.x, c1.y, c1.z, c1.w};
            #pragma unroll
            for (int i = 0; i < 8; ++i)
                #pragma unroll
                for (int j = 0; j < 8; ++j) acc[i][j] += a[i] * bb[j];
        }
        if (kt + 1 < nk) {
            int nxt = cur ^ 1;
            #pragma unroll
            for (int i = 0; i < 4; ++i) As[nxt][akh + i][arow] = ((float*)&a4)[i];
            *(float4*)&Bs[nxt][bkr][bj] = b40;
            *(float4*)&Bs[nxt][bkr][bj + 4] = b41;
        }
        __syncthreads();
    }
    #undef BROW

    #pragma unroll
    for (int i = 0; i < 8; ++i) {
        int row = (i < 4) ? (ty4 + i) : (32 + ty4 + (i - 4));
        int n = n0 + row;
        if (n < NTOT) {
            float* dst = g_mix + ((size_t)(b * NTOT + n)) * 16384 + h * 2048 + j0;
            *(float4*)(dst + tx4)      = make_float4(acc[i][0], acc[i][1], acc[i][2], acc[i][3]);
            *(float4*)(dst + 64 + tx4) = make_float4(acc[i][4], acc[i][5], acc[i][6], acc[i][7]);
        }
    }
}

// ============================================================================
// K5: out = mix @ W2^T.  FFMA 128x128x8 (R1-proven), grid (2, 800), 256 thr.
// ============================================================================
__global__ __launch_bounds__(256) void k_proj_f(float* __restrict__ out)
{
    __shared__ __align__(16) float As[2][8][128];
    __shared__ __align__(16) float Bs[2][8][128];
    int tid = threadIdx.x;
    int m0 = blockIdx.y * 128;
    int n0 = blockIdx.x * 128;

    int lrow = tid & 127;
    int lkh  = (tid >> 7) * 4;
    const float* aptr = g_mix + (size_t)(m0 + lrow) * 256 + lkh;
    const float* bptr = g_w2 + (size_t)(n0 + lrow) * 256 + lkh;

    float4 av = *(const float4*)aptr;
    float4 bv = *(const float4*)bptr;
    #pragma unroll
    for (int i = 0; i < 4; ++i) {
        As[0][lkh + i][lrow] = ((float*)&av)[i];
        Bs[0][lkh + i][lrow] = ((float*)&bv)[i];
    }
    __syncthreads();

    float acc[8][8];
    #pragma unroll
    for (int i = 0; i < 8; ++i)
        #pragma unroll
        for (int j = 0; j < 8; ++j) acc[i][j] = 0.f;

    int tx4 = (tid & 15) * 4;
    int ty4 = (tid >> 4) * 4;

    for (int kt = 0; kt < 32; ++kt) {
        int cur = kt & 1;
        if (kt < 31) {
            av = *(const float4*)(aptr + (kt + 1) * 8);
            bv = *(const float4*)(bptr + (kt + 1) * 8);
        }
        #pragma unroll
        for (int k = 0; k < 8; ++k) {
            float4 a0 = *(const float4*)&As[cur][k][ty4];
            float4 a1 = *(const float4*)&As[cur][k][64 + ty4];
            float4 b0 = *(const float4*)&Bs[cur][k][tx4];
            float4 b1 = *(const float4*)&Bs[cur][k][64 + tx4];
            float a[8] = {a0.x, a0.y, a0.z, a0.w, a1.x, a1.y, a1.z, a1.w};
            float bb[8] = {b0.x, b0.y, b0.z, b0.w, b1.x, b1.y, b1.z, b1.w};
            #pragma unroll
            for (int i = 0; i < 8; ++i)
                #pragma unroll
                for (int j = 0; j < 8; ++j) acc[i][j] += a[i] * bb[j];
        }
        if (kt < 31) {
            int nxt = cur ^ 1;
            #pragma unroll
            for (int i = 0; i < 4; ++i) {
                As[nxt][lkh + i][lrow] = ((float*)&av)[i];
                Bs[nxt][lkh + i][lrow] = ((float*)&bv)[i];
            }
        }
        __syncthreads();
    }

    #pragma unroll
    for (int i = 0; i < 8; ++i) {
        int row = (i < 4) ? (ty4 + i) : (64 + ty4 + (i - 4));
        float* c = out_pixel_ptr(out, m0 + row) + n0;
        *(float4*)(c + tx4)      = make_float4(acc[i][0], acc[i][1], acc[i][2], acc[i][3]);
        *(float4*)(c + 64 + tx4) = make_float4(acc[i][4], acc[i][5], acc[i][6], acc[i][7]);
    }
}

// ============================================================================
extern "C" void kernel_launch(void* const* d_in, const int* in_sizes, int n_in,
                              void* d_out, int out_size)
{
    const float* x1    = (const float*)d_in[0];
    const float* c1    = (const float*)d_in[1];
    const float* x2    = (const float*)d_in[2];
    const float* c2    = (const float*)d_in[3];
    const float* fqk_w = (const float*)d_in[4];
    const float* fqk_b = (const float*)d_in[5];
    const float* fqk_g = (const float*)d_in[6];
    const float* cqk_w = (const float*)d_in[7];
    const float* cqk_b = (const float*)d_in[8];
    const float* cqk_g = (const float*)d_in[9];
    const float* v_w   = (const float*)d_in[10];
    const float* vb_w  = (const float*)d_in[11];
    float* out = (float*)d_out;

    k_embed<<<400, 512>>>(x1, c1, x2, c2, fqk_w, fqk_b, fqk_g, cqk_w, cqk_b, cqk_g);
    k_wmat<<<256, 256>>>(vb_w, v_w);
    k_attn<<<dim3(NTOT, B_ * NH), 128>>>();
    k_attnv3<<<dim3(16, 7, 32), 128>>>(x1, x2);
    k_proj_f<<<dim3(2, 800), 256>>>(out);
}

// round 7
// speedup vs baseline: 1.2006x; 1.2006x over previous
#include <cuda_runtime.h>
#include <cuda_bf16.h>
#include <cstdint>
#include <math.h>

// ---- problem constants ----
#define B_    4
#define NTOT  400
#define N1    256
#define N2    144
#define DIM   256
#define NH    8

// ---- scratch ----
__device__ float g_fqk[B_ * NTOT * 512];
__device__ float g_cqk[B_ * NTOT * 128];
__device__ float g_attn[B_ * NH * NTOT * 256];
__device__ __nv_bfloat16 g_mixh[26214400];   // attn-mixed x, bf16 hi
__device__ __nv_bfloat16 g_mixl[26214400];   // bf16 lo residual
__device__ __nv_bfloat16 g_w2h[65536];       // W2 = vb_w @ v_w, bf16 hi
__device__ __nv_bfloat16 g_w2l[65536];       // bf16 lo

// ============================================================================
// helpers
// ============================================================================
__device__ __forceinline__ uint32_t smem_u32(const void* p) {
    uint32_t a;
    asm("{ .reg .u64 t; cvta.to.shared.u64 t, %1; cvt.u32.u64 %0, t; }" : "=r"(a) : "l"(p));
    return a;
}

#define LDSM_X4(r0, r1, r2, r3, addr) \
    asm volatile("ldmatrix.sync.aligned.m8n8.x4.shared.b16 {%0,%1,%2,%3}, [%4];" \
        : "=r"(r0), "=r"(r1), "=r"(r2), "=r"(r3) : "r"(addr))

#define MMA16816(d, a0, a1, a2, a3, b0, b1) \
    asm volatile("mma.sync.aligned.m16n8k16.row.col.f32.bf16.bf16.f32 " \
        "{%0,%1,%2,%3}, {%4,%5,%6,%7}, {%8,%9}, {%0,%1,%2,%3};" \
        : "+f"((d)[0]), "+f"((d)[1]), "+f"((d)[2]), "+f"((d)[3]) \
        : "r"(a0), "r"(a1), "r"(a2), "r"(a3), "r"(b0), "r"(b1))

#define CP16(dst, src) \
    asm volatile("cp.async.cg.shared.global [%0], [%1], 16;" :: "r"(dst), "l"(src))
#define CP_COMMIT() asm volatile("cp.async.commit_group;" ::: "memory")
#define CP_WAIT1()  asm volatile("cp.async.wait_group 1;" ::: "memory")
#define CP_WAIT0()  asm volatile("cp.async.wait_group 0;" ::: "memory")

__device__ __forceinline__ void cvt_split4(float4 v, uint2& hi, uint2& lo) {
    __nv_bfloat16 a = __float2bfloat16(v.x), b = __float2bfloat16(v.y);
    __nv_bfloat16 c = __float2bfloat16(v.z), d = __float2bfloat16(v.w);
    __nv_bfloat162 h0; h0.x = a; h0.y = b;
    __nv_bfloat162 h1; h1.x = c; h1.y = d;
    hi = make_uint2(*(uint32_t*)&h0, *(uint32_t*)&h1);
    __nv_bfloat162 l0, l1;
    l0.x = __float2bfloat16(v.x - __bfloat162float(a));
    l0.y = __float2bfloat16(v.y - __bfloat162float(b));
    l1.x = __float2bfloat16(v.z - __bfloat162float(c));
    l1.y = __float2bfloat16(v.w - __bfloat162float(d));
    lo = make_uint2(*(uint32_t*)&l0, *(uint32_t*)&l1);
}

// pixel maps (m = b*25600 + w*64 + p)
__device__ __forceinline__ const float* pixel_ptr(const float* __restrict__ x1,
                                                  const float* __restrict__ x2, int m) {
    int b = m / 25600;
    int r = m % 25600;
    int w = r >> 6;
    int p = r & 63;
    int py = p >> 3, px = p & 7;
    if (w < N1) {
        int y = (w >> 4) * 8 + py, xx = (w & 15) * 8 + px;
        return x1 + ((size_t)((b * 128 + y) * 128 + xx)) * DIM;
    } else {
        int w2 = w - N1;
        int y = (w2 / 12) * 8 + py, xx = (w2 % 12) * 8 + px;
        return x2 + ((size_t)((b * 96 + y) * 96 + xx)) * DIM;
    }
}
__device__ __forceinline__ float* out_pixel_ptr(float* __restrict__ out, int m) {
    int b = m / 25600;
    int r = m % 25600;
    int w = r >> 6;
    int p = r & 63;
    int py = p >> 3, px = p & 7;
    if (w < N1) {
        int y = (w >> 4) * 8 + py, xx = (w & 15) * 8 + px;
        return out + ((size_t)((b * 128 + y) * 128 + xx)) * DIM;
    } else {
        int w2 = w - N1;
        int y = (w2 / 12) * 8 + py, xx = (w2 % 12) * 8 + px;
        return out + 16777216 + ((size_t)((b * 96 + y) * 96 + xx)) * DIM;
    }
}

// ============================================================================
// K1: window means -> QK proj -> RMS.  4 windows per block.
// ============================================================================
__global__ __launch_bounds__(512) void k_embed(
    const float* __restrict__ x1, const float* __restrict__ c1,
    const float* __restrict__ x2, const float* __restrict__ c2,
    const float* __restrict__ fqk_w, const float* __restrict__ fqk_b, const float* __restrict__ fqk_g,
    const float* __restrict__ cqk_w, const float* __restrict__ cqk_b, const float* __restrict__ cqk_g)
{
    int bw = blockIdx.x;
    int b = bw / 100, wg = (bw % 100) * 4;
    __shared__ __align__(16) float favg[4][256];
    __shared__ float cavg[4][4];
    __shared__ float redf[4][16];
    __shared__ float redc[4][4];
    int t = threadIdx.x;

    {
        int tt = t & 255;
        int ws = t >> 8;
        #pragma unroll
        for (int qq = 0; qq < 2; ++qq) {
            int q = ws + qq * 2;
            int w = wg + q;
            const float* xbase;
            int rowstride;
            if (w < N1) {
                int wy = w >> 4, wx = w & 15;
                xbase = x1 + ((size_t)((b * 128 + wy * 8) * 128 + wx * 8)) * DIM;
                rowstride = 128 * DIM;
            } else {
                int w2 = w - N1;
                int wy = w2 / 12, wx = w2 % 12;
                xbase = x2 + ((size_t)((b * 96 + wy * 8) * 96 + wx * 8)) * DIM;
                rowstride = 96 * DIM;
            }
            float s = 0.f;
            #pragma unroll
            for (int py = 0; py < 8; ++py)
                #pragma unroll
                for (int px = 0; px < 8; ++px)
                    s += xbase[py * rowstride + px * DIM + tt];
            favg[q][tt] = s * (1.f / 64.f);
        }
    }
    if (t < 16) {
        int q = t >> 2, ch = t & 3;
        int w = wg + q;
        const float* cbase;
        int crowstride;
        if (w < N1) {
            int wy = w >> 4, wx = w & 15;
            cbase = c1 + ((size_t)((b * 128 + wy * 8) * 128 + wx * 8)) * 4;
            crowstride = 128 * 4;
        } else {
            int w2 = w - N1;
            int wy = w2 / 12, wx = w2 % 12;
            cbase = c2 + ((size_t)((b * 96 + wy * 8) * 96 + wx * 8)) * 4;
            crowstride = 96 * 4;
        }
        float s = 0.f;
        #pragma unroll
        for (int py = 0; py < 8; ++py)
            #pragma unroll
            for (int px = 0; px < 8; ++px)
                s += cbase[py * crowstride + px * 4 + ch];
        cavg[q][ch] = s * (1.f / 64.f);
    }
    __syncthreads();

    const float4* fw = (const float4*)(fqk_w + (size_t)t * 256);
    float raw[4];
    float bias = fqk_b[t];
    #pragma unroll
    for (int q = 0; q < 4; ++q) raw[q] = bias;
    #pragma unroll 4
    for (int d4 = 0; d4 < 64; ++d4) {
        float4 wv = fw[d4];
        #pragma unroll
        for (int q = 0; q < 4; ++q) {
            float4 av = ((const float4*)favg[q])[d4];
            raw[q] += wv.x * av.x + wv.y * av.y + wv.z * av.z + wv.w * av.w;
        }
    }
    float rawc[4];
    if (t < 128) {
        float cb = cqk_b[t];
        float w0 = cqk_w[t * 4 + 0], w1 = cqk_w[t * 4 + 1];
        float w2 = cqk_w[t * 4 + 2], w3 = cqk_w[t * 4 + 3];
        #pragma unroll
        for (int q = 0; q < 4; ++q)
            rawc[q] = cb + cavg[q][0] * w0 + cavg[q][1] * w1 + cavg[q][2] * w2 + cavg[q][3] * w3;
    }

    #pragma unroll
    for (int q = 0; q < 4; ++q) {
        float sf = raw[q] * raw[q];
        #pragma unroll
        for (int o = 16; o; o >>= 1) sf += __shfl_xor_sync(~0u, sf, o);
        if ((t & 31) == 0) redf[q][t >> 5] = sf;
    }
    if (t < 128) {
        #pragma unroll
        for (int q = 0; q < 4; ++q) {
            float sc = rawc[q] * rawc[q];
            #pragma unroll
            for (int o = 16; o; o >>= 1) sc += __shfl_xor_sync(~0u, sc, o);
            if ((t & 31) == 0) redc[q][t >> 5] = sc;
        }
    }
    __syncthreads();

    float gain = fqk_g[t];
    #pragma unroll
    for (int q = 0; q < 4; ++q) {
        float msf = 0.f;
        #pragma unroll
        for (int i = 0; i < 16; ++i) msf += redf[q][i];
        float invf = rsqrtf(msf * (1.f / 512.f) + 1e-6f);
        g_fqk[((size_t)(b * NTOT + wg + q)) * 512 + t] = raw[q] * invf * gain;
    }
    if (t < 128) {
        float cg = cqk_g[t];
        #pragma unroll
        for (int q = 0; q < 4; ++q) {
            float msc = redc[q][0] + redc[q][1] + redc[q][2] + redc[q][3];
            float invc = rsqrtf(msc * (1.f / 128.f) + 1e-6f);
            g_cqk[((size_t)(b * NTOT + wg + q)) * 128 + t] = rawc[q] * invc * cg;
        }
    }
}

// ============================================================================
// K2: W2 = vb_w @ v_w  (256x256), bf16 hi/lo split
// ============================================================================
__global__ __launch_bounds__(256) void k_wmat(const float* __restrict__ vb_w,
                                              const float* __restrict__ v_w)
{
    int i = blockIdx.x, d = threadIdx.x;
    __shared__ float vb[256];
    vb[d] = vb_w[i * 256 + d];
    __syncthreads();
    float acc = 0.f;
    #pragma unroll 8
    for (int o = 0; o < 256; ++o) acc += vb[o] * v_w[o * 256 + d];
    __nv_bfloat16 h = __float2bfloat16(acc);
    g_w2h[i * 256 + d] = h;
    g_w2l[i * 256 + d] = __float2bfloat16(acc - __bfloat162float(h));
}

// ============================================================================
// K3: scores + softmax (cross-source mask)
// ============================================================================
__global__ __launch_bounds__(128) void k_attn()
{
    int n  = blockIdx.x;
    int bh = blockIdx.y;
    int b = bh >> 3, h = bh & 7;
    int seg1 = (n >= N1);
    int colstart = seg1 ? 0 : N1;
    int cnt = seg1 ? N1 : N2;
    __shared__ float sc[256];
    __shared__ float red[4];
    int t = threadIdx.x;

    const float* qp  = g_fqk + ((size_t)(b * NTOT + n)) * 512 + h * 32;
    const float* cqp = g_cqk + ((size_t)(b * NTOT + n)) * 128 + h * 8;
    float fq[32], cq[8];
    #pragma unroll
    for (int i = 0; i < 32; ++i) fq[i] = qp[i];
    #pragma unroll
    for (int i = 0; i < 8; ++i) cq[i] = cqp[i];

    for (int m = t; m < cnt; m += 128) {
        int mg = colstart + m;
        const float* kp  = g_fqk + ((size_t)(b * NTOT + mg)) * 512 + 256 + h * 32;
        const float* ckp = g_cqk + ((size_t)(b * NTOT + mg)) * 128 + 64 + h * 8;
        float s = 0.f;
        #pragma unroll
        for (int i = 0; i < 32; ++i) s += fq[i] * kp[i];
        float s2 = 0.f;
        #pragma unroll
        for (int i = 0; i < 8; ++i) s2 += cq[i] * ckp[i];
        sc[m] = s * 0.1767766952966369f + s2 * 0.3535533905932738f;
    }
    __syncthreads();

    float mx = -1e30f;
    for (int m = t; m < cnt; m += 128) mx = fmaxf(mx, sc[m]);
    #pragma unroll
    for (int o = 16; o; o >>= 1) mx = fmaxf(mx, __shfl_xor_sync(~0u, mx, o));
    if ((t & 31) == 0) red[t >> 5] = mx;
    __syncthreads();
    mx = fmaxf(fmaxf(red[0], red[1]), fmaxf(red[2], red[3]));
    __syncthreads();

    float sum = 0.f;
    for (int m = t; m < cnt; m += 128) {
        float e = __expf(sc[m] - mx);
        sc[m] = e;
        sum += e;
    }
    #pragma unroll
    for (int o = 16; o; o >>= 1) sum += __shfl_xor_sync(~0u, sum, o);
    if ((t & 31) == 0) red[t >> 5] = sum;
    __syncthreads();
    sum = red[0] + red[1] + red[2] + red[3];
    float inv = 1.f / sum;
    float* dst = g_attn + ((size_t)(bh * NTOT + n)) * 256;
    for (int m = t; m < cnt; m += 128) dst[m] = sc[m] * inv;
}

// ============================================================================
// K4 v3: mix = attn @ x (gathered).  64x128 tiles, 128 threads, 8x8 microtile.
// Epilogue writes bf16 hi/lo split.  grid (16, 7, 32)
// ============================================================================
__global__ __launch_bounds__(128) void k_attnv3(const float* __restrict__ x1,
                                                const float* __restrict__ x2)
{
    int bh = blockIdx.z;
    int b = bh >> 3, h = bh & 7;
    int n0 = blockIdx.y * 64;
    int j0 = blockIdx.x * 128;
    int seg1 = (n0 >= N1);
    int colstart = seg1 ? 0 : N1;
    int kExt = seg1 ? N1 : N2;
    int nk = kExt >> 3;
    __shared__ __align__(16) float As[2][8][64];
    __shared__ __align__(16) float Bs[2][8][128];
    int tid = threadIdx.x;

    int arow = tid & 63;
    int akh  = (tid >> 6) * 4;
    bool avalid = (n0 + arow) < NTOT;
    int asafe = avalid ? (n0 + arow) : (NTOT - 1);
    const float* aptr = g_attn + ((size_t)(bh * NTOT + asafe)) * 256 + akh;

    int bkr = tid >> 4;
    int bj  = (tid & 15) * 8;
    int pp = 8 * h + (j0 >> 8);
    int dbase = (j0 & 255);

    #define BROW(kt) pixel_ptr(x1, x2, b * 25600 + (colstart + (kt) * 8 + bkr) * 64 + pp)

    float4 a4 = avalid ? *(const float4*)aptr : make_float4(0.f, 0.f, 0.f, 0.f);
    const float* br = BROW(0);
    float4 b40 = *(const float4*)(br + dbase + bj);
    float4 b41 = *(const float4*)(br + dbase + bj + 4);
    #pragma unroll
    for (int i = 0; i < 4; ++i) As[0][akh + i][arow] = ((float*)&a4)[i];
    *(float4*)&Bs[0][bkr][bj] = b40;
    *(float4*)&Bs[0][bkr][bj + 4] = b41;
    __syncthreads();

    float acc[8][8];
    #pragma unroll
    for (int i = 0; i < 8; ++i)
        #pragma unroll
        for (int j = 0; j < 8; ++j) acc[i][j] = 0.f;

    int tx4 = (tid & 15) * 4;
    int ty4 = (tid >> 4) * 4;

    for (int kt = 0; kt < nk; ++kt) {
        int cur = kt & 1;
        if (kt + 1 < nk) {
            a4 = avalid ? *(const float4*)(aptr + (kt + 1) * 8) : make_float4(0.f, 0.f, 0.f, 0.f);
            const float* br2 = BROW(kt + 1);
            b40 = *(const float4*)(br2 + dbase + bj);
            b41 = *(const float4*)(br2 + dbase + bj + 4);
        }
        #pragma unroll
        for (int k = 0; k < 8; ++k) {
            float4 a0 = *(const float4*)&As[cur][k][ty4];
            float4 a1 = *(const float4*)&As[cur][k][32 + ty4];
            float4 c0 = *(const float4*)&Bs[cur][k][tx4];
            float4 c1 = *(const float4*)&Bs[cur][k][64 + tx4];
            float a[8] = {a0.x, a0.y, a0.z, a0.w, a1.x, a1.y, a1.z, a1.w};
            float bb[8] = {c0.x, c0.y, c0.z, c0.w, c1.x, c1.y, c1.z, c1.w};
            #pragma unroll
            for (int i = 0; i < 8; ++i)
                #pragma unroll
                for (int j = 0; j < 8; ++j) acc[i][j] += a[i] * bb[j];
        }
        if (kt + 1 < nk) {
            int nxt = cur ^ 1;
            #pragma unroll
            for (int i = 0; i < 4; ++i) As[nxt][akh + i][arow] = ((float*)&a4)[i];
            *(float4*)&Bs[nxt][bkr][bj] = b40;
            *(float4*)&Bs[nxt][bkr][bj + 4] = b41;
        }
        __syncthreads();
    }
    #undef BROW

    #pragma unroll
    for (int i = 0; i < 8; ++i) {
        int row = (i < 4) ? (ty4 + i) : (32 + ty4 + (i - 4));
        int n = n0 + row;
        if (n < NTOT) {
            size_t idx = ((size_t)(b * NTOT + n)) * 16384 + h * 2048 + j0;
            uint2 hi, lo;
            cvt_split4(make_float4(acc[i][0], acc[i][1], acc[i][2], acc[i][3]), hi, lo);
            *(uint2*)((char*)g_mixh + (idx + tx4) * 2) = hi;
            *(uint2*)((char*)g_mixl + (idx + tx4) * 2) = lo;
            cvt_split4(make_float4(acc[i][4], acc[i][5], acc[i][6], acc[i][7]), hi, lo);
            *(uint2*)((char*)g_mixh + (idx + 64 + tx4) * 2) = hi;
            *(uint2*)((char*)g_mixl + (idx + 64 + tx4) * 2) = lo;
        }
    }
}

// ============================================================================
// K5: out = mix @ W2^T via HMMA, preconverted bf16 operands (R5-measured).
// Tile 128x128, 8 warps (32x64), K-chunk 32, cp.async double-buffer.
// ============================================================================
__global__ __launch_bounds__(256, 2)
void k_proj(float* __restrict__ Cout)
{
    extern __shared__ __align__(128) char sm[];
    uint32_t sb = smem_u32(sm);
    int tid = threadIdx.x;
    int lane = tid & 31, wid = tid >> 5;
    int wm = wid >> 1, wn = wid & 1;
    int m0 = blockIdx.y * 128, n0 = blockIdx.x * 128;

    int lrow = tid >> 1;
    int half = tid & 1;
    const char* pAh = (const char*)g_mixh + ((size_t)(m0 + lrow) * 256 + half * 16) * 2;
    const char* pAl = (const char*)g_mixl + ((size_t)(m0 + lrow) * 256 + half * 16) * 2;
    const char* pBh = (const char*)g_w2h + ((size_t)(n0 + lrow) * 256 + half * 16) * 2;
    const char* pBl = (const char*)g_w2l + ((size_t)(n0 + lrow) * 256 + half * 16) * 2;
    uint32_t dbase = (uint32_t)(lrow * 80 + half * 32);

    #define ISSUE(buf, kc) do { \
        uint32_t d0 = sb + (buf) * 40960 + dbase; \
        const char* s_; \
        s_ = pAh + (kc) * 64; CP16(d0,          s_); CP16(d0 + 16,          s_ + 16); \
        s_ = pAl + (kc) * 64; CP16(d0 + 10240,  s_); CP16(d0 + 10240 + 16,  s_ + 16); \
        s_ = pBh + (kc) * 64; CP16(d0 + 20480,  s_); CP16(d0 + 20480 + 16,  s_ + 16); \
        s_ = pBl + (kc) * 64; CP16(d0 + 30720,  s_); CP16(d0 + 30720 + 16,  s_ + 16); \
        CP_COMMIT(); \
    } while (0)

    ISSUE(0, 0);
    ISSUE(1, 1);

    float acc[2][8][4];
    #pragma unroll
    for (int mt = 0; mt < 2; ++mt)
        #pragma unroll
        for (int nt = 0; nt < 8; ++nt)
            #pragma unroll
            for (int q = 0; q < 4; ++q) acc[mt][nt][q] = 0.f;

    uint32_t lma_off = (uint32_t)((wm * 32 + (lane & 15)) * 80 + (lane >> 4) * 16);
    uint32_t lmb_off = (uint32_t)(20480 + (wn * 64 + (lane & 7) + ((lane >> 4) & 1) * 8) * 80
                                  + ((lane >> 3) & 1) * 16);

    for (int kc = 0; kc < 8; ++kc) {
        if (kc == 7) { CP_WAIT0(); } else { CP_WAIT1(); }
        __syncthreads();
        uint32_t bufb = sb + (kc & 1) * 40960;
        uint32_t lm_a = bufb + lma_off;
        uint32_t lm_b = bufb + lmb_off;
        #pragma unroll
        for (int ks = 0; ks < 2; ++ks) {
            uint32_t ka = lm_a + ks * 32;
            uint32_t kb = lm_b + ks * 32;
            uint32_t ah[2][4], al[2][4];
            LDSM_X4(ah[0][0], ah[0][1], ah[0][2], ah[0][3], ka);
            LDSM_X4(ah[1][0], ah[1][1], ah[1][2], ah[1][3], ka + 16 * 80);
            LDSM_X4(al[0][0], al[0][1], al[0][2], al[0][3], ka + 10240);
            LDSM_X4(al[1][0], al[1][1], al[1][2], al[1][3], ka + 10240 + 16 * 80);
            #pragma unroll
            for (int ng = 0; ng < 4; ++ng) {
                uint32_t bh[4], bl[4];
                LDSM_X4(bh[0], bh[1], bh[2], bh[3], kb + ng * (16 * 80));
                LDSM_X4(bl[0], bl[1], bl[2], bl[3], kb + ng * (16 * 80) + 10240);
                #pragma unroll
                for (int hf = 0; hf < 2; ++hf) {
                    int nt = ng * 2 + hf;
                    uint32_t b0 = bh[hf * 2], b1 = bh[hf * 2 + 1];
                    uint32_t l0 = bl[hf * 2], l1 = bl[hf * 2 + 1];
                    #pragma unroll
                    for (int mt = 0; mt < 2; ++mt) {
                        MMA16816(acc[mt][nt], ah[mt][0], ah[mt][1], ah[mt][2], ah[mt][3], b0, b1);
                        MMA16816(acc[mt][nt], ah[mt][0], ah[mt][1], ah[mt][2], ah[mt][3], l0, l1);
                        MMA16816(acc[mt][nt], al[mt][0], al[mt][1], al[mt][2], al[mt][3], b0, b1);
                    }
                }
            }
        }
        __syncthreads();
        if (kc + 2 < 8) ISSUE(kc & 1, kc + 2);
    }
    #undef ISSUE

    #pragma unroll
    for (int mt = 0; mt < 2; ++mt) {
        #pragma unroll
        for (int hrow = 0; hrow < 2; ++hrow) {
            int m = m0 + wm * 32 + mt * 16 + (lane >> 2) + hrow * 8;
            float* dst = out_pixel_ptr(Cout, m) + n0 + wn * 64 + (lane & 3) * 2;
            #pragma unroll
            for (int nt = 0; nt < 8; ++nt) {
                float2 v = make_float2(acc[mt][nt][hrow * 2 + 0], acc[mt][nt][hrow * 2 + 1]);
                *(float2*)(dst + nt * 8) = v;
            }
        }
    }
}

// ============================================================================
extern "C" void kernel_launch(void* const* d_in, const int* in_sizes, int n_in,
                              void* d_out, int out_size)
{
    const float* x1    = (const float*)d_in[0];
    const float* c1    = (const float*)d_in[1];
    const float* x2    = (const float*)d_in[2];
    const float* c2    = (const float*)d_in[3];
    const float* fqk_w = (const float*)d_in[4];
    const float* fqk_b = (const float*)d_in[5];
    const float* fqk_g = (const float*)d_in[6];
    const float* cqk_w = (const float*)d_in[7];
    const float* cqk_b = (const float*)d_in[8];
    const float* cqk_g = (const float*)d_in[9];
    const float* v_w   = (const float*)d_in[10];
    const float* vb_w  = (const float*)d_in[11];
    float* out = (float*)d_out;

    cudaFuncSetAttribute(k_proj, cudaFuncAttributeMaxDynamicSharedMemorySize, 81920);

    k_embed<<<400, 512>>>(x1, c1, x2, c2, fqk_w, fqk_b, fqk_g, cqk_w, cqk_b, cqk_g);
    k_wmat<<<256, 256>>>(vb_w, v_w);
    k_attn<<<dim3(NTOT, B_ * NH), 128>>>();
    k_attnv3<<<dim3(16, 7, 32), 128>>>(x1, x2);
    k_proj<<<dim3(2, 800), 256, 81920>>>(out);
}